// round 8
// baseline (speedup 1.0000x reference)
#include <cuda_runtime.h>
#include <cstdint>

#define N_NODES 500000

// Static device scratch (allocation-free rule):
// g_cs[i]  = (cos theta_i, sin theta_i)   -- 4 MB gather table
// g_acc[i] = sum over incoming edges of e^{i theta_src}  -- 4 MB accumulator
__device__ float2 g_cs[N_NODES];
__device__ float2 g_acc[N_NODES];

// ---------------------------------------------------------------------------
// Kernel 1: build (cos,sin) table, zero accumulator, AND write the v output
// (v = v0*(cos,sin) -- cos/sin already in registers).
// ---------------------------------------------------------------------------
__global__ void init_kernel(const float* __restrict__ theta,
                            const float* __restrict__ v0p,
                            float* __restrict__ out, int n) {
    int i = blockIdx.x * blockDim.x + threadIdx.x;
    if (i < n) {
        float v0 = __ldg(v0p);
        float sn, cs;
        __sincosf(theta[i], &sn, &cs);
        g_cs[i]  = make_float2(cs, sn);
        g_acc[i] = make_float2(0.f, 0.f);
        *((float2*)(out + 2 * i)) = make_float2(v0 * cs, v0 * sn);
    }
}

// ---------------------------------------------------------------------------
// Kernel 2: edge kernel, U=3 flat batch (12 edges/thread), PDL.
// sum_{e->d} e^{i(ts-td)} = e^{-i td} * sum_{e->d} e^{i ts}: per edge, gather
// only e^{i theta[src]} (8B) and RED it into acc[dst].
// Index loads are init-independent -> issued BEFORE
// cudaGridDependencySynchronize(), overlapping init's tail. All index math
// in int32 (n4 = 4M << 2^31).
// ---------------------------------------------------------------------------
__global__ void __launch_bounds__(256) edge_kernel(
        const int4* __restrict__ src4,
        const int4* __restrict__ dst4,
        int n4,
        const int* __restrict__ src_tail,
        const int* __restrict__ dst_tail,
        int n_tail) {
    const int U = 3;  // int4 groups per thread => 12 edges
    int base = blockIdx.x * (blockDim.x * U) + threadIdx.x;

    int4   s[U], d[U];
    bool   ok[U];
    float2 m[U][4];

    // Phase 1: coalesced 16B index loads (do NOT depend on init's output)
    #pragma unroll
    for (int u = 0; u < U; u++) {
        int g = base + u * blockDim.x;
        ok[u] = (g < n4);
        if (ok[u]) {
            s[u] = __ldg(&src4[g]);
            d[u] = __ldg(&dst4[g]);
        }
    }

    // Wait for init_kernel's g_cs/g_acc writes before gathering.
    cudaGridDependencySynchronize();

    // Phase 2: 12 independent random gathers (front-batched MLP)
    #pragma unroll
    for (int u = 0; u < U; u++) {
        if (ok[u]) {
            m[u][0] = __ldg(&g_cs[s[u].x]);
            m[u][1] = __ldg(&g_cs[s[u].y]);
            m[u][2] = __ldg(&g_cs[s[u].z]);
            m[u][3] = __ldg(&g_cs[s[u].w]);
        }
    }

    // Phase 3: vector reductions (float2 atomicAdd -> RED .64)
    #pragma unroll
    for (int u = 0; u < U; u++) {
        if (ok[u]) {
            atomicAdd(&g_acc[d[u].x], m[u][0]);
            atomicAdd(&g_acc[d[u].y], m[u][1]);
            atomicAdd(&g_acc[d[u].z], m[u][2]);
            atomicAdd(&g_acc[d[u].w], m[u][3]);
        }
    }

    // Tail edges (n_edges % 4): spread across the grid (n_tail==0 for 16M)
    int tslot = blockIdx.x * blockDim.x + threadIdx.x;
    if (tslot < n_tail) {
        int sidx = __ldg(&src_tail[tslot]);
        int didx = __ldg(&dst_tail[tslot]);
        atomicAdd(&g_acc[didx], __ldg(&g_cs[sidx]));
    }

    // Allow node_kernel to launch early (its acc-reads still wait on full
    // completion via its own cudaGridDependencySynchronize()).
    cudaTriggerProgrammaticLaunchCompletion();
}

// ---------------------------------------------------------------------------
// Kernel 3: torque-only node epilogue with PDL.
// Prologue loads (g_cs from init, v0/w0) overlap the edge kernel's tail;
// only the g_acc read requires the sync.
//   torque[i] = w0 * (c*S.y - s*S.x) / max(|S|, eps)
// (rotation by e^{-i t} preserves the norm; mean==sum under normalize)
// ---------------------------------------------------------------------------
__global__ void node_kernel(const float* __restrict__ v0p,
                            const float* __restrict__ w0p,
                            float* __restrict__ out,
                            int n) {
    int i = blockIdx.x * blockDim.x + threadIdx.x;

    float w0 = 0.f;
    float2 cs = make_float2(0.f, 0.f);
    if (i < n) {
        w0 = __ldg(w0p);
        cs = __ldg(&g_cs[i]);
    }

    // Wait for edge_kernel's atomics to be complete & visible.
    cudaGridDependencySynchronize();

    if (i < n) {
        float2 S = g_acc[i];
        float y   = cs.x * S.y - cs.y * S.x;
        float nrm = sqrtf(S.x * S.x + S.y * S.y);
        out[2 * n + i] = w0 * (y / fmaxf(nrm, 1e-12f));
    }
}

// ---------------------------------------------------------------------------
extern "C" void kernel_launch(void* const* d_in, const int* in_sizes, int n_in,
                              void* d_out, int out_size) {
    const float* theta = (const float*)d_in[0];
    const int*   src   = (const int*)d_in[1];
    const int*   dst   = (const int*)d_in[2];
    const float* v0p   = (const float*)d_in[3];
    const float* w0p   = (const float*)d_in[4];
    float*       out   = (float*)d_out;

    int n_nodes = in_sizes[0];
    int n_edges = in_sizes[1];
    int n4      = n_edges / 4;
    int n_tail  = n_edges - n4 * 4;

    // Kernel 1: plain launch
    {
        int threads = 256;
        int blocks = (n_nodes + threads - 1) / threads;
        init_kernel<<<blocks, threads>>>(theta, v0p, out, n_nodes);
    }

    // Kernel 2: PDL launch (prologue overlaps init's tail)
    {
        const int U = 3;
        int threads = 256;
        int per_block = threads * U;
        int blocks = (n4 + per_block - 1) / per_block;
        if (blocks < 1) blocks = 1;

        cudaLaunchConfig_t cfg = {};
        cfg.gridDim  = dim3((unsigned)blocks, 1, 1);
        cfg.blockDim = dim3(256, 1, 1);
        cfg.dynamicSmemBytes = 0;
        cfg.stream = 0;
        cudaLaunchAttribute attrs[1];
        attrs[0].id = cudaLaunchAttributeProgrammaticStreamSerialization;
        attrs[0].val.programmaticStreamSerializationAllowed = 1;
        cfg.attrs = attrs;
        cfg.numAttrs = 1;
        cudaLaunchKernelEx(&cfg, edge_kernel,
                           (const int4*)src, (const int4*)dst, n4,
                           (const int*)(src + n4 * 4),
                           (const int*)(dst + n4 * 4), n_tail);
    }

    // Kernel 3: PDL launch (prologue overlaps edge's tail)
    {
        int threads = 256;
        int blocks = (n_nodes + threads - 1) / threads;

        cudaLaunchConfig_t cfg = {};
        cfg.gridDim  = dim3((unsigned)blocks, 1, 1);
        cfg.blockDim = dim3((unsigned)threads, 1, 1);
        cfg.dynamicSmemBytes = 0;
        cfg.stream = 0;
        cudaLaunchAttribute attrs[1];
        attrs[0].id = cudaLaunchAttributeProgrammaticStreamSerialization;
        attrs[0].val.programmaticStreamSerializationAllowed = 1;
        cfg.attrs = attrs;
        cfg.numAttrs = 1;
        cudaLaunchKernelEx(&cfg, node_kernel, v0p, w0p, out, n_nodes);
    }
}

// round 9
// speedup vs baseline: 1.0442x; 1.0442x over previous
#include <cuda_runtime.h>
#include <cstdint>

#define N_NODES 500000

// Static device scratch (allocation-free rule):
// g_cs[i]  = (cos theta_i, sin theta_i)   -- 4 MB gather table
// g_acc[i] = sum over incoming edges of e^{i theta_src}  -- 4 MB accumulator
__device__ float2 g_cs[N_NODES];
__device__ float2 g_acc[N_NODES];

// ---------------------------------------------------------------------------
// Kernel 1: build (cos,sin) table, zero accumulator, AND write the v output
// (v = v0*(cos,sin) -- cos/sin already in registers).
// ---------------------------------------------------------------------------
__global__ void init_kernel(const float* __restrict__ theta,
                            const float* __restrict__ v0p,
                            float* __restrict__ out, int n) {
    int i = blockIdx.x * blockDim.x + threadIdx.x;
    if (i < n) {
        float v0 = __ldg(v0p);
        float sn, cs;
        __sincosf(theta[i], &sn, &cs);
        g_cs[i]  = make_float2(cs, sn);
        g_acc[i] = make_float2(0.f, 0.f);
        *((float2*)(out + 2 * i)) = make_float2(v0 * cs, v0 * sn);
    }
}

// ---------------------------------------------------------------------------
// Kernel 2: edge kernel, U=2 flat batch (8 edges/thread -- measured optimum:
// 4/iter=138us, 8=127.1us, 12=133.1us, 16=221.6us), PDL.
// sum_{e->d} e^{i(ts-td)} = e^{-i td} * sum_{e->d} e^{i ts}: per edge, gather
// only e^{i theta[src]} (8B) and RED it into acc[dst].
// Index loads are init-independent -> issued BEFORE
// cudaGridDependencySynchronize(). PDL trigger fires after the gathers
// (REDs still outstanding): node_kernel's launch+prologue overlaps the
// RED-drain; its acc-reads wait on full completion via its own sync.
// ---------------------------------------------------------------------------
__global__ void __launch_bounds__(256) edge_kernel(
        const int4* __restrict__ src4,
        const int4* __restrict__ dst4,
        int n4,
        const int* __restrict__ src_tail,
        const int* __restrict__ dst_tail,
        int n_tail) {
    const int U = 2;  // int4 groups per thread => 8 edges
    int base = blockIdx.x * (blockDim.x * U) + threadIdx.x;

    int4   s[U], d[U];
    bool   ok[U];
    float2 m[U][4];

    // Phase 1: coalesced 16B index loads (do NOT depend on init's output)
    #pragma unroll
    for (int u = 0; u < U; u++) {
        int g = base + u * blockDim.x;
        ok[u] = (g < n4);
        if (ok[u]) {
            s[u] = __ldg(&src4[g]);
            d[u] = __ldg(&dst4[g]);
        }
    }

    // Wait for init_kernel's g_cs/g_acc writes before gathering.
    cudaGridDependencySynchronize();

    // Phase 2: 8 independent random gathers (front-batched MLP)
    #pragma unroll
    for (int u = 0; u < U; u++) {
        if (ok[u]) {
            m[u][0] = __ldg(&g_cs[s[u].x]);
            m[u][1] = __ldg(&g_cs[s[u].y]);
            m[u][2] = __ldg(&g_cs[s[u].z]);
            m[u][3] = __ldg(&g_cs[s[u].w]);
        }
    }

    // Early PDL trigger: allows node_kernel to begin launching while our
    // REDs drain. Correctness is preserved -- the secondary's
    // cudaGridDependencySynchronize() waits for THIS grid's completion.
    cudaTriggerProgrammaticLaunchCompletion();

    // Phase 3: vector reductions (float2 atomicAdd -> RED .64)
    #pragma unroll
    for (int u = 0; u < U; u++) {
        if (ok[u]) {
            atomicAdd(&g_acc[d[u].x], m[u][0]);
            atomicAdd(&g_acc[d[u].y], m[u][1]);
            atomicAdd(&g_acc[d[u].z], m[u][2]);
            atomicAdd(&g_acc[d[u].w], m[u][3]);
        }
    }

    // Tail edges (n_edges % 4): spread across the grid (0 for E=16M)
    int tslot = blockIdx.x * blockDim.x + threadIdx.x;
    if (tslot < n_tail) {
        int sidx = __ldg(&src_tail[tslot]);
        int didx = __ldg(&dst_tail[tslot]);
        atomicAdd(&g_acc[didx], __ldg(&g_cs[sidx]));
    }
}

// ---------------------------------------------------------------------------
// Kernel 3: torque-only node epilogue with PDL.
// Prologue loads (g_cs from init, w0) overlap the edge kernel's RED drain;
// only the g_acc read requires the sync.
//   torque[i] = w0 * (c*S.y - s*S.x) / max(|S|, eps)
// (rotation by e^{-i t} preserves the norm; mean==sum under normalize)
// ---------------------------------------------------------------------------
__global__ void node_kernel(const float* __restrict__ v0p,
                            const float* __restrict__ w0p,
                            float* __restrict__ out,
                            int n) {
    int i = blockIdx.x * blockDim.x + threadIdx.x;

    float w0 = 0.f;
    float2 cs = make_float2(0.f, 0.f);
    if (i < n) {
        w0 = __ldg(w0p);
        cs = __ldg(&g_cs[i]);
    }

    // Wait for edge_kernel's atomics to be complete & visible.
    cudaGridDependencySynchronize();

    if (i < n) {
        float2 S = g_acc[i];
        float y   = cs.x * S.y - cs.y * S.x;
        float nrm = sqrtf(S.x * S.x + S.y * S.y);
        out[2 * n + i] = w0 * (y / fmaxf(nrm, 1e-12f));
    }
}

// ---------------------------------------------------------------------------
extern "C" void kernel_launch(void* const* d_in, const int* in_sizes, int n_in,
                              void* d_out, int out_size) {
    const float* theta = (const float*)d_in[0];
    const int*   src   = (const int*)d_in[1];
    const int*   dst   = (const int*)d_in[2];
    const float* v0p   = (const float*)d_in[3];
    const float* w0p   = (const float*)d_in[4];
    float*       out   = (float*)d_out;

    int n_nodes = in_sizes[0];
    int n_edges = in_sizes[1];
    int n4      = n_edges / 4;
    int n_tail  = n_edges - n4 * 4;

    // Kernel 1: plain launch
    {
        int threads = 256;
        int blocks = (n_nodes + threads - 1) / threads;
        init_kernel<<<blocks, threads>>>(theta, v0p, out, n_nodes);
    }

    // Kernel 2: PDL launch (prologue overlaps init's tail)
    {
        const int U = 2;
        int threads = 256;
        int per_block = threads * U;
        int blocks = (n4 + per_block - 1) / per_block;
        if (blocks < 1) blocks = 1;

        cudaLaunchConfig_t cfg = {};
        cfg.gridDim  = dim3((unsigned)blocks, 1, 1);
        cfg.blockDim = dim3(256, 1, 1);
        cfg.dynamicSmemBytes = 0;
        cfg.stream = 0;
        cudaLaunchAttribute attrs[1];
        attrs[0].id = cudaLaunchAttributeProgrammaticStreamSerialization;
        attrs[0].val.programmaticStreamSerializationAllowed = 1;
        cfg.attrs = attrs;
        cfg.numAttrs = 1;
        cudaLaunchKernelEx(&cfg, edge_kernel,
                           (const int4*)src, (const int4*)dst, n4,
                           (const int*)(src + n4 * 4),
                           (const int*)(dst + n4 * 4), n_tail);
    }

    // Kernel 3: PDL launch (prologue overlaps edge's RED drain)
    {
        int threads = 256;
        int blocks = (n_nodes + threads - 1) / threads;

        cudaLaunchConfig_t cfg = {};
        cfg.gridDim  = dim3((unsigned)blocks, 1, 1);
        cfg.blockDim = dim3((unsigned)threads, 1, 1);
        cfg.dynamicSmemBytes = 0;
        cfg.stream = 0;
        cudaLaunchAttribute attrs[1];
        attrs[0].id = cudaLaunchAttributeProgrammaticStreamSerialization;
        attrs[0].val.programmaticStreamSerializationAllowed = 1;
        cfg.attrs = attrs;
        cfg.numAttrs = 1;
        cudaLaunchKernelEx(&cfg, node_kernel, v0p, w0p, out, n_nodes);
    }
}

// round 10
// speedup vs baseline: 1.0444x; 1.0003x over previous
#include <cuda_runtime.h>
#include <cstdint>

#define N_NODES 500000

// Static device scratch (allocation-free rule):
// g_cs[i]  = (cos theta_i, sin theta_i)   -- 4 MB gather table
// g_acc[i] = sum over incoming edges of e^{i theta_src}  -- 4 MB accumulator
__device__ float2 g_cs[N_NODES];
__device__ float2 g_acc[N_NODES];

// ---------------------------------------------------------------------------
// Kernel 1: build (cos,sin) table + zero accumulator ONLY.
// (v output moved to node_kernel's PDL prologue -- off the critical path.)
// ---------------------------------------------------------------------------
__global__ void init_kernel(const float* __restrict__ theta, int n) {
    int i = blockIdx.x * blockDim.x + threadIdx.x;
    if (i < n) {
        float sn, cs;
        __sincosf(theta[i], &sn, &cs);
        g_cs[i]  = make_float2(cs, sn);
        g_acc[i] = make_float2(0.f, 0.f);
    }
}

// ---------------------------------------------------------------------------
// Kernel 2: edge kernel, U=2 flat batch (8 edges/thread -- measured optimum:
// 4/iter=138us, 8=127.1us, 12=133.1us, 16=221.6us), PDL.
// sum_{e->d} e^{i(ts-td)} = e^{-i td} * sum_{e->d} e^{i ts}: per edge, gather
// only e^{i theta[src]} (8B) and RED it into acc[dst].
// Index loads are init-independent -> issued BEFORE
// cudaGridDependencySynchronize(). PDL trigger fires after the gathers;
// node_kernel's acc-reads still wait on full completion via its own sync.
// ---------------------------------------------------------------------------
__global__ void __launch_bounds__(256) edge_kernel(
        const int4* __restrict__ src4,
        const int4* __restrict__ dst4,
        int n4,
        const int* __restrict__ src_tail,
        const int* __restrict__ dst_tail,
        int n_tail) {
    const int U = 2;  // int4 groups per thread => 8 edges
    int base = blockIdx.x * (blockDim.x * U) + threadIdx.x;

    int4   s[U], d[U];
    bool   ok[U];
    float2 m[U][4];

    // Phase 1: coalesced 16B index loads (do NOT depend on init's output)
    #pragma unroll
    for (int u = 0; u < U; u++) {
        int g = base + u * blockDim.x;
        ok[u] = (g < n4);
        if (ok[u]) {
            s[u] = __ldg(&src4[g]);
            d[u] = __ldg(&dst4[g]);
        }
    }

    // Wait for init_kernel's g_cs/g_acc writes before gathering.
    cudaGridDependencySynchronize();

    // Phase 2: 8 independent random gathers (front-batched MLP)
    #pragma unroll
    for (int u = 0; u < U; u++) {
        if (ok[u]) {
            m[u][0] = __ldg(&g_cs[s[u].x]);
            m[u][1] = __ldg(&g_cs[s[u].y]);
            m[u][2] = __ldg(&g_cs[s[u].z]);
            m[u][3] = __ldg(&g_cs[s[u].w]);
        }
    }

    // Early PDL trigger: node_kernel may begin launching while REDs drain.
    // Its cudaGridDependencySynchronize() waits for THIS grid's completion.
    cudaTriggerProgrammaticLaunchCompletion();

    // Phase 3: vector reductions (float2 atomicAdd -> RED .64)
    #pragma unroll
    for (int u = 0; u < U; u++) {
        if (ok[u]) {
            atomicAdd(&g_acc[d[u].x], m[u][0]);
            atomicAdd(&g_acc[d[u].y], m[u][1]);
            atomicAdd(&g_acc[d[u].z], m[u][2]);
            atomicAdd(&g_acc[d[u].w], m[u][3]);
        }
    }

    // Tail edges (n_edges % 4): spread across the grid (0 for E=16M)
    int tslot = blockIdx.x * blockDim.x + threadIdx.x;
    if (tslot < n_tail) {
        int sidx = __ldg(&src_tail[tslot]);
        int didx = __ldg(&dst_tail[tslot]);
        atomicAdd(&g_acc[didx], __ldg(&g_cs[sidx]));
    }
}

// ---------------------------------------------------------------------------
// Kernel 3: node epilogue with PDL.
// Prologue (BEFORE the sync): load g_cs (init's output -- init is complete,
// node only launches after edge's trigger which gates on init) and WRITE the
// v output. This 8 MB of traffic runs inside the edge-drain overlap window.
// After the sync: torque from g_acc.
//   torque[i] = w0 * (c*S.y - s*S.x) / max(|S|, eps)
// (rotation by e^{-i t} preserves the norm; mean==sum under normalize)
// ---------------------------------------------------------------------------
__global__ void node_kernel(const float* __restrict__ v0p,
                            const float* __restrict__ w0p,
                            float* __restrict__ out,
                            int n) {
    int i = blockIdx.x * blockDim.x + threadIdx.x;

    float w0 = 0.f;
    float2 cs = make_float2(0.f, 0.f);
    if (i < n) {
        float v0 = __ldg(v0p);
        w0 = __ldg(w0p);
        cs = __ldg(&g_cs[i]);
        // v output: depends only on init, store during the overlap window
        *((float2*)(out + 2 * i)) = make_float2(v0 * cs.x, v0 * cs.y);
    }

    // Wait for edge_kernel's atomics to be complete & visible.
    cudaGridDependencySynchronize();

    if (i < n) {
        float2 S = g_acc[i];
        float y   = cs.x * S.y - cs.y * S.x;
        float nrm = sqrtf(S.x * S.x + S.y * S.y);
        out[2 * n + i] = w0 * (y / fmaxf(nrm, 1e-12f));
    }
}

// ---------------------------------------------------------------------------
extern "C" void kernel_launch(void* const* d_in, const int* in_sizes, int n_in,
                              void* d_out, int out_size) {
    const float* theta = (const float*)d_in[0];
    const int*   src   = (const int*)d_in[1];
    const int*   dst   = (const int*)d_in[2];
    const float* v0p   = (const float*)d_in[3];
    const float* w0p   = (const float*)d_in[4];
    float*       out   = (float*)d_out;

    int n_nodes = in_sizes[0];
    int n_edges = in_sizes[1];
    int n4      = n_edges / 4;
    int n_tail  = n_edges - n4 * 4;

    // Kernel 1: plain launch
    {
        int threads = 256;
        int blocks = (n_nodes + threads - 1) / threads;
        init_kernel<<<blocks, threads>>>(theta, n_nodes);
    }

    // Kernel 2: PDL launch (prologue overlaps init's tail)
    {
        const int U = 2;
        int threads = 256;
        int per_block = threads * U;
        int blocks = (n4 + per_block - 1) / per_block;
        if (blocks < 1) blocks = 1;

        cudaLaunchConfig_t cfg = {};
        cfg.gridDim  = dim3((unsigned)blocks, 1, 1);
        cfg.blockDim = dim3(256, 1, 1);
        cfg.dynamicSmemBytes = 0;
        cfg.stream = 0;
        cudaLaunchAttribute attrs[1];
        attrs[0].id = cudaLaunchAttributeProgrammaticStreamSerialization;
        attrs[0].val.programmaticStreamSerializationAllowed = 1;
        cfg.attrs = attrs;
        cfg.numAttrs = 1;
        cudaLaunchKernelEx(&cfg, edge_kernel,
                           (const int4*)src, (const int4*)dst, n4,
                           (const int*)(src + n4 * 4),
                           (const int*)(dst + n4 * 4), n_tail);
    }

    // Kernel 3: PDL launch (prologue: v store + g_cs loads, overlaps edge
    // drain; torque after the sync)
    {
        int threads = 256;
        int blocks = (n_nodes + threads - 1) / threads;

        cudaLaunchConfig_t cfg = {};
        cfg.gridDim  = dim3((unsigned)blocks, 1, 1);
        cfg.blockDim = dim3((unsigned)threads, 1, 1);
        cfg.dynamicSmemBytes = 0;
        cfg.stream = 0;
        cudaLaunchAttribute attrs[1];
        attrs[0].id = cudaLaunchAttributeProgrammaticStreamSerialization;
        attrs[0].val.programmaticStreamSerializationAllowed = 1;
        cfg.attrs = attrs;
        cfg.numAttrs = 1;
        cudaLaunchKernelEx(&cfg, node_kernel, v0p, w0p, out, n_nodes);
    }
}